// round 5
// baseline (speedup 1.0000x reference)
#include <cuda_runtime.h>
#include <cuda_bf16.h>
#include <cstdint>

// ExpertGather: y[b,e,k,j] = sum_i x[b, Ind[b,e,k], i] * W[e,i,j]
// B=8, T=2048, I=1024, E=16, K=256, J=1024. fp32 in/out, Ind int32 on device.
//
// Round 5: harness compiles for plain sm_100 (no 'a') -> tcgen05 unavailable.
// Use portable tensor-core ISA instead: mma.sync.m16n8k16 bf16 with hi/lo
// split (hi*hi + hi*lo + lo*hi -> ~1e-5 rel err), fp32 register accumulators.
//  - CTA 128x128, 8 warps (2x4), warp tile 64x32, K chunks of 32,
//    double-buffered smem, one __syncthreads per chunk, register prefetch.
//  - A smem [m][k] bf16, row stride 40 halves (conflict-free frag LDS).
//  - B smem [k][n] bf16, row stride 136 halves (odd*16B -> ldmatrix clean),
//    fragments via ldmatrix.x4.trans.

namespace {
constexpr int Bv = 8, Tv = 2048, Iv = 1024, Ev = 16, Kv = 256, Jv = 1024;
constexpr int BM = 128, BN = 128, CK = 32;
constexpr int NCHUNK = Iv / CK;          // 32
constexpr int THREADS = 256;

constexpr int SA = 40;                   // A row stride, halves
constexpr int SB = 136;                  // B row stride, halves
constexpr uint32_t A_TILE_B = BM * SA * 2;   // 10240
constexpr uint32_t B_TILE_B = CK * SB * 2;   // 8704

constexpr uint32_t OFF_AHI = 0;                       // [2] bufs
constexpr uint32_t OFF_ALO = 2 * A_TILE_B;            // 20480
constexpr uint32_t OFF_BHI = OFF_ALO + 2 * A_TILE_B;  // 40960
constexpr uint32_t OFF_BLO = OFF_BHI + 2 * B_TILE_B;  // 58368
constexpr uint32_t SMEM_BYTES = OFF_BLO + 2 * B_TILE_B;  // 75776
}

__device__ __forceinline__ uint32_t smem_u32(const void* p) {
    uint32_t a;
    asm("{ .reg .u64 t; cvta.to.shared.u64 t, %1; cvt.u32.u64 %0, t; }"
        : "=r"(a) : "l"(p));
    return a;
}

__device__ __forceinline__ void split4(float4 v, uint2& hi, uint2& lo) {
    __nv_bfloat162 h01 = __floats2bfloat162_rn(v.x, v.y);
    __nv_bfloat162 h23 = __floats2bfloat162_rn(v.z, v.w);
    __nv_bfloat162 l01 = __floats2bfloat162_rn(v.x - __bfloat162float(h01.x),
                                               v.y - __bfloat162float(h01.y));
    __nv_bfloat162 l23 = __floats2bfloat162_rn(v.z - __bfloat162float(h23.x),
                                               v.w - __bfloat162float(h23.y));
    hi.x = *reinterpret_cast<uint32_t*>(&h01);
    hi.y = *reinterpret_cast<uint32_t*>(&h23);
    lo.x = *reinterpret_cast<uint32_t*>(&l01);
    lo.y = *reinterpret_cast<uint32_t*>(&l23);
}

__device__ __forceinline__ void ldsm4t(uint32_t* r, uint32_t addr) {
    asm volatile(
        "ldmatrix.sync.aligned.m8n8.x4.trans.shared.b16 {%0,%1,%2,%3}, [%4];"
        : "=r"(r[0]), "=r"(r[1]), "=r"(r[2]), "=r"(r[3]) : "r"(addr));
}

__device__ __forceinline__ void mma_bf16(float* c, const uint32_t* a,
                                         uint32_t b0, uint32_t b1) {
    asm volatile(
        "mma.sync.aligned.m16n8k16.row.col.f32.bf16.bf16.f32 "
        "{%0,%1,%2,%3}, {%4,%5,%6,%7}, {%8,%9}, {%0,%1,%2,%3};"
        : "+f"(c[0]), "+f"(c[1]), "+f"(c[2]), "+f"(c[3])
        : "r"(a[0]), "r"(a[1]), "r"(a[2]), "r"(a[3]), "r"(b0), "r"(b1));
}

__global__ __launch_bounds__(THREADS)
void expert_gather_mma_kernel(const float* __restrict__ x,
                              const float* __restrict__ W,
                              const int* __restrict__ Ind,
                              float* __restrict__ y)
{
    extern __shared__ char smem[];
    __shared__ int sRow[BM];
    const uint32_t sb = smem_u32(smem);

    const int tid = threadIdx.x;
    const int wid = tid >> 5;
    const int lid = tid & 31;
    const int g   = lid >> 2;           // group 0..7
    const int t2  = (lid & 3) * 2;      // 2*tig

    const int bz = blockIdx.z;          // e*8 + b  (e slowest -> W L2 reuse)
    const int e  = bz >> 3;
    const int b  = bz & 7;
    const int mBlock = blockIdx.y;      // 0..1
    const int nBlock = blockIdx.x;      // 0..7

    const int wm = wid & 1;             // warp m index (0..1) -> 64 rows
    const int wn = wid >> 1;            // warp n index (0..3) -> 32 cols

    // Gather row offsets for this M-tile. Ind is int32 (JAX x64 disabled).
    if (tid < BM) {
        int t = Ind[(b * Ev + e) * Kv + mBlock * BM + tid];
        sRow[tid] = (b * Tv + t) * Iv;
    }
    __syncthreads();

    // ---- gmem load mappings ----
    // A: pass i: row (tid>>3)+i*32, cols (tid&7)*4 .. +3 (within chunk)
    const int ak = (tid & 7) * 4;
    int rowOff[4];
    #pragma unroll
    for (int i = 0; i < 4; ++i) rowOff[i] = sRow[(tid >> 3) + i * 32];
    // B: pass i: k-row (tid>>5)+i*8, cols (tid&31)*4 (within BN)
    const float* wbase = W + ((size_t)e << 20) + (size_t)(tid >> 5) * Jv
                           + nBlock * BN + (tid & 31) * 4;

    // ---- smem store byte offsets ----
    uint32_t aSt[4], bSt[4];
    #pragma unroll
    for (int i = 0; i < 4; ++i) {
        aSt[i] = (uint32_t)(((tid >> 3) + i * 32) * (SA * 2) + (tid & 7) * 8);
        bSt[i] = (uint32_t)(((tid >> 5) + i * 8) * (SB * 2) + (tid & 31) * 8);
    }

    float acc[4][4][4];
    #pragma unroll
    for (int mt = 0; mt < 4; ++mt)
        #pragma unroll
        for (int nt = 0; nt < 4; ++nt)
            #pragma unroll
            for (int q = 0; q < 4; ++q) acc[mt][nt][q] = 0.0f;

    // Prefetch chunk 0.
    float4 aV[4], bV[4];
    #pragma unroll
    for (int i = 0; i < 4; ++i) {
        aV[i] = *reinterpret_cast<const float4*>(x + rowOff[i] + ak);
        bV[i] = *reinterpret_cast<const float4*>(wbase + (size_t)(i * 8) * Jv);
    }

    // ldmatrix source addresses (per lane), within a buffer:
    //   k = ks*16 + ((lid>>3)&1)*8 + (lid&7), n = wn*32 + np*16 + (lid>>4)*8
    const int lk = ((lid >> 3) & 1) * 8 + (lid & 7);
    const int ln = wn * 32 + (lid >> 4) * 8;

    int buf = 0;
    for (int c = 0; c < NCHUNK; ++c) {
        const uint32_t aHiB = OFF_AHI + buf * A_TILE_B;
        const uint32_t aLoB = OFF_ALO + buf * A_TILE_B;
        const uint32_t bHiB = OFF_BHI + buf * B_TILE_B;
        const uint32_t bLoB = OFF_BLO + buf * B_TILE_B;

        // Commit prefetched chunk to smem (split hi/lo).
        #pragma unroll
        for (int i = 0; i < 4; ++i) {
            uint2 hi, lo;
            split4(aV[i], hi, lo);
            *reinterpret_cast<uint2*>(smem + aHiB + aSt[i]) = hi;
            *reinterpret_cast<uint2*>(smem + aLoB + aSt[i]) = lo;
            split4(bV[i], hi, lo);
            *reinterpret_cast<uint2*>(smem + bHiB + bSt[i]) = hi;
            *reinterpret_cast<uint2*>(smem + bLoB + bSt[i]) = lo;
        }
        __syncthreads();

        // Prefetch next chunk (overlaps with the MMA work below).
        if (c + 1 < NCHUNK) {
            const int kt = (c + 1) * CK;
            #pragma unroll
            for (int i = 0; i < 4; ++i) {
                aV[i] = *reinterpret_cast<const float4*>(
                    x + rowOff[i] + kt + ak);
                bV[i] = *reinterpret_cast<const float4*>(
                    wbase + (size_t)(kt + i * 8) * Jv);
            }
        }

        #pragma unroll
        for (int ks = 0; ks < 2; ++ks) {
            // B fragments for this k16: 2 ldmatrix.x4.trans per split.
            uint32_t bH[8], bL[8];
            #pragma unroll
            for (int np = 0; np < 2; ++np) {
                uint32_t off = (uint32_t)((ks * 16 + lk) * (SB * 2)
                                          + (ln + np * 16) * 2);
                ldsm4t(bH + np * 4, sb + bHiB + off);
                ldsm4t(bL + np * 4, sb + bLoB + off);
            }
            #pragma unroll
            for (int mt = 0; mt < 4; ++mt) {
                const int row0 = wm * 64 + mt * 16 + g;
                uint32_t o00 = (uint32_t)((row0)     * (SA * 2) + (ks * 16 + t2) * 2);
                uint32_t o10 = (uint32_t)((row0 + 8) * (SA * 2) + (ks * 16 + t2) * 2);
                uint32_t aH[4], aL[4];
                aH[0] = *reinterpret_cast<const uint32_t*>(smem + aHiB + o00);
                aH[1] = *reinterpret_cast<const uint32_t*>(smem + aHiB + o10);
                aH[2] = *reinterpret_cast<const uint32_t*>(smem + aHiB + o00 + 16);
                aH[3] = *reinterpret_cast<const uint32_t*>(smem + aHiB + o10 + 16);
                aL[0] = *reinterpret_cast<const uint32_t*>(smem + aLoB + o00);
                aL[1] = *reinterpret_cast<const uint32_t*>(smem + aLoB + o10);
                aL[2] = *reinterpret_cast<const uint32_t*>(smem + aLoB + o00 + 16);
                aL[3] = *reinterpret_cast<const uint32_t*>(smem + aLoB + o10 + 16);

                #pragma unroll
                for (int nt = 0; nt < 4; ++nt) {
                    mma_bf16(acc[mt][nt], aH, bH[nt * 2], bH[nt * 2 + 1]);
                    mma_bf16(acc[mt][nt], aH, bL[nt * 2], bL[nt * 2 + 1]);
                    mma_bf16(acc[mt][nt], aL, bH[nt * 2], bH[nt * 2 + 1]);
                }
            }
        }
        buf ^= 1;
        // Safe without trailing barrier: writes to this buffer at c+2 occur
        // after barrier c+1, which readers at c pass only post-compute.
    }

    // ---- epilogue ----
    const size_t ybase = ((size_t)(b * Ev + e) * Kv + mBlock * BM) * Jv
                         + nBlock * BN;
    #pragma unroll
    for (int mt = 0; mt < 4; ++mt) {
        const int row0 = wm * 64 + mt * 16 + g;
        #pragma unroll
        for (int nt = 0; nt < 4; ++nt) {
            const int col = wn * 32 + nt * 8 + t2;
            float2 v0 = make_float2(acc[mt][nt][0], acc[mt][nt][1]);
            float2 v1 = make_float2(acc[mt][nt][2], acc[mt][nt][3]);
            *reinterpret_cast<float2*>(y + ybase + (size_t)row0 * Jv + col) = v0;
            *reinterpret_cast<float2*>(y + ybase + (size_t)(row0 + 8) * Jv + col) = v1;
        }
    }
}

extern "C" void kernel_launch(void* const* d_in, const int* in_sizes, int n_in,
                              void* d_out, int out_size)
{
    const float* x   = (const float*)d_in[0];  // [8, 2048, 1024] f32
    const float* W   = (const float*)d_in[1];  // [16, 1024, 1024] f32
    const int*   Ind = (const int*)d_in[2];    // [8, 16, 256] i32 (JAX x64 off)
    float*       y   = (float*)d_out;          // [8, 16, 256, 1024] f32
    (void)in_sizes; (void)n_in; (void)out_size;

    static int attr_set = 0;
    if (!attr_set) {
        cudaFuncSetAttribute(expert_gather_mma_kernel,
                             cudaFuncAttributeMaxDynamicSharedMemorySize,
                             SMEM_BYTES);
        attr_set = 1;
    }

    dim3 grid(Jv / BN, Kv / BM, Bv * Ev);  // (8, 2, 128)
    expert_gather_mma_kernel<<<grid, THREADS, SMEM_BYTES>>>(x, W, Ind, y);
}

// round 6
// speedup vs baseline: 2.1519x; 2.1519x over previous
#include <cuda_runtime.h>
#include <cuda_fp16.h>
#include <cstdint>

// ExpertGather: y[b,e,k,j] = sum_i x[b, Ind[b,e,k], i] * W[e,i,j]
// B=8, T=2048, I=1024, E=16, K=256, J=1024. fp32 in/out, Ind int32 on device.
//
// Round 6: single-pass fp16 mma (norm-based rel_err ~4e-4 < 1e-3) with a
// one-time fp32->fp16 prep into __device__ scratch, then a cp.async
// 3-stage-pipelined GEMM:
//  - CTA 128x128, 8 warps (2x4), warp tile 64x32, K chunks of 64
//  - A smem [128][64] f16, XOR-swizzled 16B chunks, ldmatrix.x4 (non-trans)
//  - B smem [64][128] f16, XOR-swizzled, ldmatrix.x4.trans (R5-validated map)
//  - __launch_bounds__(256,2) -> 2 CTAs/SM

namespace {
constexpr int Bv = 8, Tv = 2048, Iv = 1024, Ev = 16, Kv = 256, Jv = 1024;
constexpr int BM = 128, BN = 128, CK = 64;
constexpr int NCHUNK = Iv / CK;          // 16
constexpr int THREADS = 256;
constexpr int STAGES = 3;

constexpr uint32_t A_STAGE = BM * CK * 2;     // 16384 B
constexpr uint32_t B_STAGE = CK * BN * 2;     // 16384 B
constexpr uint32_t OFF_A = 0;
constexpr uint32_t OFF_B = STAGES * A_STAGE;  // 49152
constexpr uint32_t SMEM_BYTES = OFF_B + STAGES * B_STAGE;  // 98304
}

__device__ __half2 g_xh[(size_t)Bv * Tv * Iv / 2];   // 32 MB scratch
__device__ __half2 g_Wh[(size_t)Ev * Iv * Jv / 2];   // 32 MB scratch

__device__ __forceinline__ uint32_t smem_u32(const void* p) {
    uint32_t a;
    asm("{ .reg .u64 t; cvta.to.shared.u64 t, %1; cvt.u32.u64 %0, t; }"
        : "=r"(a) : "l"(p));
    return a;
}

#define CP_ASYNC16(dst, src)                                              \
    asm volatile("cp.async.cg.shared.global [%0], [%1], 16;"              \
                 :: "r"(dst), "l"(src) : "memory")
#define CP_COMMIT() asm volatile("cp.async.commit_group;" ::: "memory")
#define CP_WAIT(n)  asm volatile("cp.async.wait_group %0;" :: "n"(n) : "memory")

__device__ __forceinline__ void ldsm4(uint32_t* r, uint32_t addr) {
    asm volatile(
        "ldmatrix.sync.aligned.m8n8.x4.shared.b16 {%0,%1,%2,%3}, [%4];"
        : "=r"(r[0]), "=r"(r[1]), "=r"(r[2]), "=r"(r[3]) : "r"(addr));
}
__device__ __forceinline__ void ldsm4t(uint32_t* r, uint32_t addr) {
    asm volatile(
        "ldmatrix.sync.aligned.m8n8.x4.trans.shared.b16 {%0,%1,%2,%3}, [%4];"
        : "=r"(r[0]), "=r"(r[1]), "=r"(r[2]), "=r"(r[3]) : "r"(addr));
}
__device__ __forceinline__ void mma_f16(float* c, const uint32_t* a,
                                        uint32_t b0, uint32_t b1) {
    asm volatile(
        "mma.sync.aligned.m16n8k16.row.col.f32.f16.f16.f32 "
        "{%0,%1,%2,%3}, {%4,%5,%6,%7}, {%8,%9}, {%0,%1,%2,%3};"
        : "+f"(c[0]), "+f"(c[1]), "+f"(c[2]), "+f"(c[3])
        : "r"(a[0]), "r"(a[1]), "r"(a[2]), "r"(a[3]), "r"(b0), "r"(b1));
}

// ---- prep: fp32 -> fp16 for x and W ----
__global__ __launch_bounds__(256)
void prep_half_kernel(const float* __restrict__ x, const float* __restrict__ W)
{
    const int NX4 = Bv * Tv * Iv / 4;      // 4,194,304 float4 in x
    const int NW4 = Ev * Iv * Jv / 4;      // 4,194,304 float4 in W
    const int total = NX4 + NW4;
    const int stride = gridDim.x * blockDim.x;
    for (int v = blockIdx.x * blockDim.x + threadIdx.x; v < total; v += stride) {
        float4 f;
        __half2* dst;
        if (v < NX4) {
            f = reinterpret_cast<const float4*>(x)[v];
            dst = g_xh + (size_t)v * 2;
        } else {
            f = reinterpret_cast<const float4*>(W)[v - NX4];
            dst = g_Wh + (size_t)(v - NX4) * 2;
        }
        __half2 h0 = __floats2half2_rn(f.x, f.y);
        __half2 h1 = __floats2half2_rn(f.z, f.w);
        dst[0] = h0;
        dst[1] = h1;
    }
}

// ---- main GEMM ----
__global__ __launch_bounds__(THREADS, 2)
void expert_gather_mma_kernel(const int* __restrict__ Ind,
                              float* __restrict__ y)
{
    extern __shared__ char smem[];
    __shared__ int sRow[BM];
    const uint32_t sb = smem_u32(smem);
    const __half* xh = reinterpret_cast<const __half*>(g_xh);
    const __half* Wh = reinterpret_cast<const __half*>(g_Wh);

    const int tid = threadIdx.x;
    const int wid = tid >> 5;
    const int lid = tid & 31;

    const int bz = blockIdx.z;          // e*8 + b  (e slowest -> W L2 reuse)
    const int e  = bz >> 3;
    const int b  = bz & 7;
    const int mBlock = blockIdx.y;      // 0..1
    const int nBlock = blockIdx.x;      // 0..7

    const int wm = wid & 1;             // warp m (0..1) -> 64 rows
    const int wn = wid >> 1;            // warp n (0..3) -> 32 cols

    if (tid < BM) {
        int t = Ind[(b * Ev + e) * Kv + mBlock * BM + tid];  // int32!
        sRow[tid] = (b * Tv + t) * Iv;   // element offset into xh
    }
    __syncthreads();

    // ---- cp.async mappings ----
    // A: 128 rows x 8 chunks(16B); thread: row=tid>>1, chunks (tid&1)*4+i
    const int arow = tid >> 1;
    const int ach0 = (tid & 1) * 4;
    const __half* aSrcBase = xh + sRow[arow] + ach0 * 8;
    uint32_t aDst[4];
    #pragma unroll
    for (int i = 0; i < 4; ++i) {
        int ch = ach0 + i;
        aDst[i] = (uint32_t)(arow * 128 + ((ch ^ (arow & 7)) << 4));
    }
    // B: 64 rows x 16 chunks; thread: row=tid>>2, chunks (tid&3)*4+i
    const int brow = tid >> 2;
    const int bch0 = (tid & 3) * 4;
    const __half* bSrcBase = Wh + ((size_t)e << 20) + (size_t)brow * Jv
                               + nBlock * BN + bch0 * 8;
    uint32_t bDst[4];
    #pragma unroll
    for (int i = 0; i < 4; ++i) {
        int ch = bch0 + i;
        bDst[i] = (uint32_t)(brow * 256 + ((ch ^ (brow & 7)) << 4));
    }

    // ---- ldmatrix lane constants ----
    // A (non-trans m16k16): row = wm*64 + mt*16 + (lid&7) + ((lid>>3)&1)*8
    //                       chunk = ks*2 + (lid>>4)
    const int aLr = (lid & 7) + ((lid >> 3) & 1) * 8;
    const int aLc = lid >> 4;
    // B (trans, R5-validated): row = ks*16 + lk; chunk = wn*4 + (lid>>4) + np*2
    const int lk  = ((lid >> 3) & 1) * 8 + (lid & 7);
    const int bLc = wn * 4 + (lid >> 4);

    float acc[4][4][4];
    #pragma unroll
    for (int mt = 0; mt < 4; ++mt)
        #pragma unroll
        for (int nt = 0; nt < 4; ++nt)
            #pragma unroll
            for (int q = 0; q < 4; ++q) acc[mt][nt][q] = 0.0f;

    // ---- pipeline prologue: issue stages 0..STAGES-2 ----
    #pragma unroll
    for (int s = 0; s < STAGES - 1; ++s) {
        const uint32_t aB = sb + OFF_A + s * A_STAGE;
        const uint32_t bB = sb + OFF_B + s * B_STAGE;
        const int kt = s * CK;
        #pragma unroll
        for (int i = 0; i < 4; ++i) {
            CP_ASYNC16(aB + aDst[i], aSrcBase + kt + i * 8);
            CP_ASYNC16(bB + bDst[i], bSrcBase + (size_t)kt * Jv + i * 8);
        }
        CP_COMMIT();
    }

    for (int c = 0; c < NCHUNK; ++c) {
        CP_WAIT(STAGES - 2);   // group c complete
        __syncthreads();

        // Issue stage c+STAGES-1 (buffer was fully consumed at iter c-1).
        if (c + STAGES - 1 < NCHUNK) {
            const int s = (c + STAGES - 1) % STAGES;
            const uint32_t aB = sb + OFF_A + s * A_STAGE;
            const uint32_t bB = sb + OFF_B + s * B_STAGE;
            const int kt = (c + STAGES - 1) * CK;
            #pragma unroll
            for (int i = 0; i < 4; ++i) {
                CP_ASYNC16(aB + aDst[i], aSrcBase + kt + i * 8);
                CP_ASYNC16(bB + bDst[i], bSrcBase + (size_t)kt * Jv + i * 8);
            }
        }
        CP_COMMIT();   // commit even when empty to keep group counts aligned

        const uint32_t aB = sb + OFF_A + (c % STAGES) * A_STAGE;
        const uint32_t bB = sb + OFF_B + (c % STAGES) * B_STAGE;

        #pragma unroll
        for (int ks = 0; ks < CK / 16; ++ks) {
            uint32_t bF[8];
            #pragma unroll
            for (int np = 0; np < 2; ++np) {
                const int row = ks * 16 + lk;
                const int ch  = bLc + np * 2;
                ldsm4t(bF + np * 4,
                       bB + (uint32_t)(row * 256 + ((ch ^ (row & 7)) << 4)));
            }
            #pragma unroll
            for (int mt = 0; mt < 4; ++mt) {
                const int row = wm * 64 + mt * 16 + aLr;
                const int ch  = ks * 2 + aLc;
                uint32_t aF[4];
                ldsm4(aF, aB + (uint32_t)(row * 128 + ((ch ^ (row & 7)) << 4)));
                #pragma unroll
                for (int nt = 0; nt < 4; ++nt)
                    mma_f16(acc[mt][nt], aF, bF[nt * 2], bF[nt * 2 + 1]);
            }
        }
        __syncthreads();   // all warps done reading buffer c before reuse
    }

    // ---- epilogue (same mapping as R5, validated) ----
    const int g  = lid >> 2;
    const int t2 = (lid & 3) * 2;
    const size_t ybase = ((size_t)(b * Ev + e) * Kv + mBlock * BM) * Jv
                         + nBlock * BN;
    #pragma unroll
    for (int mt = 0; mt < 4; ++mt) {
        const int row0 = wm * 64 + mt * 16 + g;
        #pragma unroll
        for (int nt = 0; nt < 4; ++nt) {
            const int col = wn * 32 + nt * 8 + t2;
            float2 v0 = make_float2(acc[mt][nt][0], acc[mt][nt][1]);
            float2 v1 = make_float2(acc[mt][nt][2], acc[mt][nt][3]);
            *reinterpret_cast<float2*>(y + ybase + (size_t)row0 * Jv + col) = v0;
            *reinterpret_cast<float2*>(y + ybase + (size_t)(row0 + 8) * Jv + col) = v1;
        }
    }
}

extern "C" void kernel_launch(void* const* d_in, const int* in_sizes, int n_in,
                              void* d_out, int out_size)
{
    const float* x   = (const float*)d_in[0];  // [8, 2048, 1024] f32
    const float* W   = (const float*)d_in[1];  // [16, 1024, 1024] f32
    const int*   Ind = (const int*)d_in[2];    // [8, 16, 256] i32 (JAX x64 off)
    float*       y   = (float*)d_out;          // [8, 16, 256, 1024] f32
    (void)in_sizes; (void)n_in; (void)out_size;

    static int attr_set = 0;
    if (!attr_set) {
        cudaFuncSetAttribute(expert_gather_mma_kernel,
                             cudaFuncAttributeMaxDynamicSharedMemorySize,
                             SMEM_BYTES);
        attr_set = 1;
    }

    prep_half_kernel<<<4096, 256>>>(x, W);

    dim3 grid(Jv / BN, Kv / BM, Bv * Ev);  // (8, 2, 128)
    expert_gather_mma_kernel<<<grid, THREADS, SMEM_BYTES>>>(Ind, y);
}